// round 1
// baseline (speedup 1.0000x reference)
#include <cuda_runtime.h>

// CliffordISTA on GB300 — Round 0: correct fp32 baseline with f32x2-packed SIMT GEMMs.
//
// Math: x_{t+1} = shrink(x_t - STEP * K_bwd^T(K_fwd^T x_t - y)), 50 iters.
// K_fwd[(n,i),(m,k)] = s(i, i^k) * A[m,n,i^k]
// K_bwd[(m,i),(n,k)] = s(i, i^k) * rev[i^k] * A[m,n,i^k]
// with s(a,b) the Cl(3,0) reorder sign (metric all +1) and rev the reversion sign.

#define BDIM 64
#define NB 8
#define MDIM 256
#define NDIM 512
#define NI (NDIM * NB)   // 4096 = inner dim of fwd, out cols of bwd
#define MI (MDIM * NB)   // 2048 = out cols of fwd, inner dim of bwd
#define NITER 50
#define STEPF 0.01f
#define BK 32

// Scratch (static device globals — no runtime allocation allowed).
__device__ float g_Kf[(size_t)NI * MI];      // [k = n*8+i][c = m*8+kb]   32 MB
__device__ float g_Kb[(size_t)MI * NI];      // [k = m*8+i][c = n*8+kb]   32 MB
__device__ float g_xA[NI * BDIM];            // x ping  (transposed [ni][b])
__device__ float g_xB[NI * BDIM];            // x pong
__device__ float g_err[MI * BDIM];           // err transposed [mi][b]
__device__ float g_yT[MI * BDIM];            // y transposed   [mk][b]
__device__ float g_pf[4 * MI * BDIM];        // fwd split-K partials
__device__ float g_pb[2 * NI * BDIM];        // bwd split-K partials

__device__ __forceinline__ float csign(int i, int j) {
    // reorder sign for e_i * e_j in Cl(3,0): parity of sum_t popc((i>>t) & j)
    int cnt = __popc((i >> 1) & j) + __popc((i >> 2) & j);
    return (cnt & 1) ? -1.0f : 1.0f;
}

__global__ void build_kf(const float* __restrict__ A) {
    int idx = blockIdx.x * blockDim.x + threadIdx.x;
    if (idx >= NI * MI) return;
    int k = idx / MI, c = idx - k * MI;
    int n = k >> 3, i = k & 7;
    int m = c >> 3, kb = c & 7;
    int j = i ^ kb;
    g_Kf[idx] = csign(i, j) * A[(m * NDIM + n) * NB + j];
}

__global__ void build_kb(const float* __restrict__ A) {
    int idx = blockIdx.x * blockDim.x + threadIdx.x;
    if (idx >= MI * NI) return;
    int k = idx / NI, c = idx - k * NI;
    int m = k >> 3, i = k & 7;
    int n = c >> 3, kb = c & 7;
    int j = i ^ kb;
    float rv = (__popc(j) >= 2) ? -1.0f : 1.0f;   // reversion sign on blade j
    g_Kb[idx] = csign(i, j) * rv * A[(m * NDIM + n) * NB + j];
}

__global__ void build_yT(const float* __restrict__ y) {
    int idx = blockIdx.x * blockDim.x + threadIdx.x;  // MI*BDIM
    if (idx >= MI * BDIM) return;
    int c = idx >> 6, b = idx & 63;
    g_yT[idx] = y[b * MI + c];
}

__global__ void zero_buf(float* __restrict__ p, int n) {
    int idx = blockIdx.x * blockDim.x + threadIdx.x;
    if (idx < n) p[idx] = 0.0f;
}

// out[c0..c0+63][0..63] += xT[k0..k0+kchunk)[64] @ Km[k][c], written to split-K partial.
// Thread tile: 4 rows x 4 cols via 8 packed fma.rn.f32x2 per k-step.
__global__ __launch_bounds__(256) void gemm64(
    const float* __restrict__ xT,   // [Ktot][64]
    const float* __restrict__ Km,   // [Ktot][Ctot] (k-major)
    float* __restrict__ part,       // [gridDim.y][Ctot*64]
    int Ctot, int kchunk)
{
    __shared__ float  xs[BK * 64];
    __shared__ float2 ks[BK * 64];  // K values pre-duplicated into f32x2
    const int c0 = blockIdx.x * 64;
    const int k0 = blockIdx.y * kchunk;
    const int tid = threadIdx.x;
    const int tx = tid & 15;        // col group: cols {tx, tx+16, tx+32, tx+48}
    const int ty = tid >> 4;        // row group: rows 4*ty .. 4*ty+3

    unsigned long long acc[2][4];
#pragma unroll
    for (int p = 0; p < 2; p++)
#pragma unroll
        for (int j = 0; j < 4; j++) acc[p][j] = 0ull;

    for (int kt = 0; kt < kchunk; kt += BK) {
        // Stage X slice [BK][64] — linear float4 copy, coalesced.
        const float4* xsrc = reinterpret_cast<const float4*>(xT + (size_t)(k0 + kt) * 64);
        float4* xdst = reinterpret_cast<float4*>(xs);
        xdst[tid] = xsrc[tid];
        xdst[tid + 256] = xsrc[tid + 256];
        // Stage K tile [BK][64] duplicated to float2 {v,v}.
#pragma unroll
        for (int r = 0; r < 2; r++) {
            int lin4 = tid + r * 256;
            int kk = lin4 >> 4;
            int c4 = (lin4 & 15) << 2;
            float4 v = *reinterpret_cast<const float4*>(
                Km + (size_t)(k0 + kt + kk) * Ctot + c0 + c4);
            ks[kk * 64 + c4 + 0] = make_float2(v.x, v.x);
            ks[kk * 64 + c4 + 1] = make_float2(v.y, v.y);
            ks[kk * 64 + c4 + 2] = make_float2(v.z, v.z);
            ks[kk * 64 + c4 + 3] = make_float2(v.w, v.w);
        }
        __syncthreads();
#pragma unroll
        for (int kk = 0; kk < BK; kk++) {
            // rows 4ty..4ty+3 of x at this k, as two packed f32x2 (LDS.128, broadcast)
            const unsigned long long* xp =
                reinterpret_cast<const unsigned long long*>(&xs[kk * 64 + ty * 4]);
            unsigned long long x0 = xp[0];
            unsigned long long x1 = xp[1];
#pragma unroll
            for (int j = 0; j < 4; j++) {
                // 8B lane stride -> 32 banks covered exactly once, conflict-free
                unsigned long long kd = *reinterpret_cast<const unsigned long long*>(
                    &ks[kk * 64 + tx + 16 * j]);
                asm("fma.rn.f32x2 %0, %1, %2, %0;" : "+l"(acc[0][j]) : "l"(x0), "l"(kd));
                asm("fma.rn.f32x2 %0, %1, %2, %0;" : "+l"(acc[1][j]) : "l"(x1), "l"(kd));
            }
        }
        __syncthreads();
    }

    float* po = part + (size_t)blockIdx.y * Ctot * 64;
#pragma unroll
    for (int j = 0; j < 4; j++) {
        int c = c0 + tx + 16 * j;
        *reinterpret_cast<float2*>(po + (size_t)c * 64 + ty * 4) =
            *reinterpret_cast<float2*>(&acc[0][j]);
        *reinterpret_cast<float2*>(po + (size_t)c * 64 + ty * 4 + 2) =
            *reinterpret_cast<float2*>(&acc[1][j]);
    }
}

__global__ void err_reduce() {
    int idx = blockIdx.x * blockDim.x + threadIdx.x;  // MI*BDIM
    if (idx >= MI * BDIM) return;
    float s = g_pf[idx] + g_pf[idx + MI * BDIM]
            + g_pf[idx + 2 * MI * BDIM] + g_pf[idx + 3 * MI * BDIM];
    g_err[idx] = s - g_yT[idx];
}

__global__ void update_x(const float* __restrict__ xin, float* __restrict__ xout) {
    int idx = blockIdx.x * blockDim.x + threadIdx.x;  // NI*BDIM
    if (idx >= NI * BDIM) return;
    int c = idx >> 6;
    int kb = c & 7;
    float g = g_pb[idx] + g_pb[idx + NI * BDIM];
    float xv = xin[idx] - STEPF * g;
    // thresholds per blade grade: g0->0, g1/g2->0.001, g3->0.002
    float thr = (kb == 0) ? 0.0f : ((kb == 7) ? 0.002f : 0.001f);
    float a = fabsf(xv) - thr;
    xout[idx] = (a > 0.0f) ? copysignf(a, xv) : 0.0f;
}

__global__ void write_out(const float* __restrict__ xin, float* __restrict__ out) {
    int idx = blockIdx.x * blockDim.x + threadIdx.x;  // BDIM*NI
    if (idx >= BDIM * NI) return;
    int b = idx >> 12;
    int c = idx & (NI - 1);
    out[idx] = xin[c * 64 + b];   // out[b][n][k] = xT[nk][b]
}

extern "C" void kernel_launch(void* const* d_in, const int* in_sizes, int n_in,
                              void* d_out, int out_size)
{
    const float* y = (const float*)d_in[0];
    const float* A = (const float*)d_in[1];
    if (n_in >= 2 && in_sizes[0] > in_sizes[1]) {  // defensive: y has 131072 elems, A 1048576
        const float* t = y; y = A; A = t;
    }

    float *kf, *kb, *xA, *xB, *er, *pf, *pb;
    cudaGetSymbolAddress((void**)&kf, g_Kf);
    cudaGetSymbolAddress((void**)&kb, g_Kb);
    cudaGetSymbolAddress((void**)&xA, g_xA);
    cudaGetSymbolAddress((void**)&xB, g_xB);
    cudaGetSymbolAddress((void**)&er, g_err);
    cudaGetSymbolAddress((void**)&pf, g_pf);
    cudaGetSymbolAddress((void**)&pb, g_pb);

    build_kf<<<(NI * MI + 255) / 256, 256>>>(A);
    build_kb<<<(MI * NI + 255) / 256, 256>>>(A);
    build_yT<<<(MI * BDIM + 255) / 256, 256>>>(y);
    zero_buf<<<(NI * BDIM + 255) / 256, 256>>>(xA, NI * BDIM);

    float* xcur = xA;
    float* xnxt = xB;
    for (int it = 0; it < NITER; it++) {
        // fwd: Ax partials = x @ K_fwd   (Ctot=2048, K=4096 split 4)
        gemm64<<<dim3(MI / 64, 4), 256>>>(xcur, kf, pf, MI, NI / 4);
        err_reduce<<<(MI * BDIM + 255) / 256, 256>>>();
        // bwd: grad partials = err @ K_bwd (Ctot=4096, K=2048 split 2)
        gemm64<<<dim3(NI / 64, 2), 256>>>(er, kb, pb, NI, MI / 2);
        update_x<<<(NI * BDIM + 255) / 256, 256>>>(xcur, xnxt);
        float* t = xcur; xcur = xnxt; xnxt = t;
    }
    write_out<<<(BDIM * NI + 255) / 256, 256>>>(xcur, (float*)d_out);
}

// round 3
// speedup vs baseline: 4.6217x; 4.6217x over previous
#include <cuda_runtime.h>
#include <cuda_bf16.h>
#include <cstdint>

// CliffordISTA — Round 3: mma.sync (HMMA) bf16 hi/lo split GEMM.
// out[c][b] = sum_k KT[c][k] * x[b][k];  v = hi + lo (bf16 split),
// D += Ahi*Bhi + Ahi*Blo + Alo*Bhi  (lo*lo dropped ~2^-16), fp32 accum.
// tcgen05 is unavailable (harness PTX targets compute_103, not 103a);
// ldmatrix + mma.sync.m16n8k16 are baseline features and hit the tensor pipe.

#define BDIM 64
#define NB 8
#define MDIM 256
#define NDIM 512
#define NI 4096          // fwd inner dim / bwd out cols
#define MI 2048          // fwd out cols / bwd inner dim
#define NITER 50
#define STEPF 0.01f
#define KT 64            // K elems (bf16) per stage = 128B rows
#define MT 128           // M tile per CTA
#define FWD_SPLIT 8
#define BWD_SPLIT 4

#define BUF_BYTES 49152  // per stage: A_hi 16K | A_lo 16K | B_hi 8K | B_lo 8K
#define SMEM_TOTAL (2 * BUF_BYTES)

// ---------------- device globals ----------------
__device__ __nv_bfloat16 g_Kf_hi[(size_t)MI * NI];   // KfT[c][k], c=m*8+kb, k=n*8+i
__device__ __nv_bfloat16 g_Kf_lo[(size_t)MI * NI];
__device__ __nv_bfloat16 g_Kb_hi[(size_t)NI * MI];   // KbT[c][k], c=n*8+kb, k=m*8+i
__device__ __nv_bfloat16 g_Kb_lo[(size_t)NI * MI];
__device__ __nv_bfloat16 g_x_hi[BDIM * NI];          // x[b][k]
__device__ __nv_bfloat16 g_x_lo[BDIM * NI];
__device__ __nv_bfloat16 g_e_hi[BDIM * MI];          // err[b][k]
__device__ __nv_bfloat16 g_e_lo[BDIM * MI];
__device__ float g_xA[BDIM * NI];
__device__ float g_xB[BDIM * NI];
__device__ float g_pf[(size_t)FWD_SPLIT * MI * BDIM];
__device__ float g_pb[(size_t)BWD_SPLIT * NI * BDIM];

// ---------------- helpers ----------------
__device__ __forceinline__ uint32_t smem_u32(const void* p) {
    uint32_t a;
    asm("{ .reg .u64 t; cvta.to.shared.u64 t, %1; cvt.u32.u64 %0, t; }" : "=r"(a) : "l"(p));
    return a;
}

#define CP_ASYNC16(smem, gptr) \
    asm volatile("cp.async.cg.shared.global [%0], [%1], 16;" :: "r"(smem), "l"(gptr))
#define CP_COMMIT() asm volatile("cp.async.commit_group;" ::: "memory")
#define CP_WAIT1()  asm volatile("cp.async.wait_group 1;" ::: "memory")
#define CP_WAIT0()  asm volatile("cp.async.wait_group 0;" ::: "memory")

__device__ __forceinline__ void ldsm4(uint32_t* r, uint32_t addr) {
    asm volatile("ldmatrix.sync.aligned.m8n8.x4.shared.b16 {%0,%1,%2,%3}, [%4];"
                 : "=r"(r[0]), "=r"(r[1]), "=r"(r[2]), "=r"(r[3]) : "r"(addr));
}

__device__ __forceinline__ void mma_bf16(float* c, const uint32_t* a, uint32_t b0, uint32_t b1) {
    asm volatile(
        "mma.sync.aligned.m16n8k16.row.col.f32.bf16.bf16.f32 "
        "{%0,%1,%2,%3}, {%4,%5,%6,%7}, {%8,%9}, {%0,%1,%2,%3};"
        : "+f"(c[0]), "+f"(c[1]), "+f"(c[2]), "+f"(c[3])
        : "r"(a[0]), "r"(a[1]), "r"(a[2]), "r"(a[3]), "r"(b0), "r"(b1));
}

__device__ __forceinline__ float csign(int i, int j) {
    int cnt = __popc((i >> 1) & j) + __popc((i >> 2) & j);
    return (cnt & 1) ? -1.0f : 1.0f;
}

__device__ __forceinline__ void split_bf16(float v, __nv_bfloat16* hi, __nv_bfloat16* lo) {
    __nv_bfloat16 h = __float2bfloat16(v);
    *hi = h;
    *lo = __float2bfloat16(v - __bfloat162float(h));
}

// ---------------- build / elementwise ----------------
__global__ void build_kf(const float* __restrict__ A) {
    size_t idx = (size_t)blockIdx.x * blockDim.x + threadIdx.x;
    if (idx >= (size_t)MI * NI) return;
    int c = (int)(idx >> 12), k = (int)(idx & (NI - 1));
    int m = c >> 3, kb = c & 7, n = k >> 3, i = k & 7, j = i ^ kb;
    float v = csign(i, j) * A[(m * NDIM + n) * NB + j];
    split_bf16(v, &g_Kf_hi[idx], &g_Kf_lo[idx]);
}

__global__ void build_kb(const float* __restrict__ A) {
    size_t idx = (size_t)blockIdx.x * blockDim.x + threadIdx.x;
    if (idx >= (size_t)NI * MI) return;
    int c = (int)(idx >> 11), k = (int)(idx & (MI - 1));
    int n = c >> 3, kb = c & 7, m = k >> 3, i = k & 7, j = i ^ kb;
    float rv = (__popc(j) >= 2) ? -1.0f : 1.0f;
    float v = csign(i, j) * rv * A[(m * NDIM + n) * NB + j];
    split_bf16(v, &g_Kb_hi[idx], &g_Kb_lo[idx]);
}

__global__ void init_x() {
    int idx = blockIdx.x * blockDim.x + threadIdx.x;
    if (idx >= BDIM * NI) return;
    g_xA[idx] = 0.0f;
    g_x_hi[idx] = __float2bfloat16(0.0f);
    g_x_lo[idx] = __float2bfloat16(0.0f);
}

__global__ void err_conv(const float* __restrict__ y) {
    int idx = blockIdx.x * blockDim.x + threadIdx.x;   // [b][c], c<MI
    if (idx >= BDIM * MI) return;
    int b = idx >> 11, c = idx & (MI - 1);
    float s = 0.0f;
#pragma unroll
    for (int t = 0; t < FWD_SPLIT; t++) s += g_pf[(size_t)t * MI * 64 + c * 64 + b];
    float e = s - y[idx];
    split_bf16(e, &g_e_hi[idx], &g_e_lo[idx]);
}

__global__ void upd_x(const float* __restrict__ xin, float* __restrict__ xout) {
    int idx = blockIdx.x * blockDim.x + threadIdx.x;   // [b][c], c<NI
    if (idx >= BDIM * NI) return;
    int b = idx >> 12, c = idx & (NI - 1), kb = c & 7;
    float g = 0.0f;
#pragma unroll
    for (int t = 0; t < BWD_SPLIT; t++) g += g_pb[(size_t)t * NI * 64 + c * 64 + b];
    float xv = xin[idx] - STEPF * g;
    float thr = (kb == 0) ? 0.0f : ((kb == 7) ? 0.002f : 0.001f);
    float a = fabsf(xv) - thr;
    float r = (a > 0.0f) ? copysignf(a, xv) : 0.0f;
    xout[idx] = r;
    split_bf16(r, &g_x_hi[idx], &g_x_lo[idx]);
}

// ---------------- mma.sync gemm ----------------
struct GemmArgs {
    const __nv_bfloat16 *Ahi, *Alo, *Bhi, *Blo;
    float* part;
    int Kdim;      // row stride (= total K)
    int Ctot;      // total output rows
    int kchunk;    // K per split-K chunk
};

__device__ __forceinline__ void issue_stage(
    uint32_t sb, int buf, int tid, const GemmArgs& ga, int c0, int kk)
{
    uint32_t base = sb + buf * BUF_BYTES;
#pragma unroll
    for (int r = 0; r < 12; r++) {
        int q = tid + (r << 8);                // 3072 16B chunks per stage
        const __nv_bfloat16* gp;
        uint32_t tb;
        int row, cc;
        if (q < 2048) {                        // A: 128 rows x 8 chunks, hi | lo
            int half = q >> 10, qq = q & 1023;
            row = qq >> 3; cc = qq & 7;
            gp = (half ? ga.Alo : ga.Ahi) + (size_t)(c0 + row) * ga.Kdim + kk + cc * 8;
            tb = base + half * 16384;
        } else {                               // B: 64 rows x 8 chunks, hi | lo
            int q2 = q - 2048;
            int half = q2 >> 9, qq = q2 & 511;
            row = qq >> 3; cc = qq & 7;
            gp = (half ? ga.Blo : ga.Bhi) + (size_t)row * ga.Kdim + kk + cc * 8;
            tb = base + 32768 + half * 8192;
        }
        uint32_t off = (uint32_t)((row << 7) | ((cc ^ (row & 7)) << 4));  // XOR swizzle
        CP_ASYNC16(tb + off, gp);
    }
    CP_COMMIT();
}

__global__ __launch_bounds__(256, 1) void gemm_mma(GemmArgs ga) {
    extern __shared__ char smem[];
    uint32_t sb = smem_u32(smem);
    const int tid = threadIdx.x;
    const int c0 = blockIdx.x * MT;
    const int k0 = blockIdx.y * ga.kchunk;
    const int nst = ga.kchunk / KT;

    const int warp = tid >> 5, lane = tid & 31;
    const int wm = warp >> 1;          // 0..3 -> m offset wm*32
    const int wn = warp & 1;           // 0..1 -> n offset wn*32
    const int lrow = lane & 15;        // ldmatrix row within 16
    const int lhalf = lane >> 4;       // ldmatrix 16B half select
    const int lsw = lrow & 7;          // swizzle key

    float acc[2][4][4];
#pragma unroll
    for (int am = 0; am < 2; am++)
#pragma unroll
        for (int ng = 0; ng < 4; ng++)
#pragma unroll
            for (int v = 0; v < 4; v++) acc[am][ng][v] = 0.0f;

    issue_stage(sb, 0, tid, ga, c0, k0);

    for (int s = 0; s < nst; s++) {
        if (s + 1 < nst) {
            issue_stage(sb, (s + 1) & 1, tid, ga, c0, k0 + (s + 1) * KT);
            CP_WAIT1();
        } else {
            CP_COMMIT();   // keep group count consistent
            CP_WAIT0();
        }
        __syncthreads();

        uint32_t bufb = sb + (s & 1) * BUF_BYTES;
#pragma unroll
        for (int p = 0; p < 3; p++) {
            uint32_t Ab = bufb + (p == 2 ? 16384u : 0u);
            uint32_t Bb = bufb + 32768u + (p == 1 ? 8192u : 0u);
#pragma unroll
            for (int kk = 0; kk < 4; kk++) {
                uint32_t ksel = (uint32_t)(((kk << 1) | lhalf) ^ lsw) << 4;
                uint32_t a[2][4], b[2][4];
#pragma unroll
                for (int am = 0; am < 2; am++) {
                    int row = wm * 32 + am * 16 + lrow;
                    ldsm4(a[am], Ab + (uint32_t)(row << 7) + ksel);
                }
#pragma unroll
                for (int bn = 0; bn < 2; bn++) {
                    int row = wn * 32 + bn * 16 + lrow;
                    ldsm4(b[bn], Bb + (uint32_t)(row << 7) + ksel);
                }
#pragma unroll
                for (int am = 0; am < 2; am++)
#pragma unroll
                    for (int ng = 0; ng < 4; ng++) {
                        int bn = ng >> 1, sel = ng & 1;
                        mma_bf16(acc[am][ng], a[am], b[bn][sel], b[bn][sel + 2]);
                    }
            }
        }
        __syncthreads();
    }

    // epilogue: thread holds (row = qrow, qrow+8; col = qcol2, qcol2+1) per tile
    const int qrow = lane >> 2, qcol2 = (lane & 3) << 1;
    float* po = ga.part + (size_t)blockIdx.y * ga.Ctot * 64;
#pragma unroll
    for (int am = 0; am < 2; am++)
#pragma unroll
        for (int ng = 0; ng < 4; ng++) {
            int c = c0 + wm * 32 + am * 16 + qrow;
            int col = wn * 32 + ng * 8 + qcol2;
            *reinterpret_cast<float2*>(&po[(size_t)c * 64 + col]) =
                make_float2(acc[am][ng][0], acc[am][ng][1]);
            *reinterpret_cast<float2*>(&po[(size_t)(c + 8) * 64 + col]) =
                make_float2(acc[am][ng][2], acc[am][ng][3]);
        }
}

// ---------------- host ----------------
extern "C" void kernel_launch(void* const* d_in, const int* in_sizes, int n_in,
                              void* d_out, int out_size)
{
    const float* y = (const float*)d_in[0];
    const float* A = (const float*)d_in[1];
    if (n_in >= 2 && in_sizes[0] > in_sizes[1]) {
        const float* t = y; y = A; A = t;
    }

    cudaFuncSetAttribute(gemm_mma, cudaFuncAttributeMaxDynamicSharedMemorySize, SMEM_TOTAL);

    __nv_bfloat16 *kfh, *kfl, *kbh, *kbl, *xh, *xl, *eh, *el;
    float *xA, *xB, *pf, *pb;
    cudaGetSymbolAddress((void**)&kfh, g_Kf_hi);
    cudaGetSymbolAddress((void**)&kfl, g_Kf_lo);
    cudaGetSymbolAddress((void**)&kbh, g_Kb_hi);
    cudaGetSymbolAddress((void**)&kbl, g_Kb_lo);
    cudaGetSymbolAddress((void**)&xh, g_x_hi);
    cudaGetSymbolAddress((void**)&xl, g_x_lo);
    cudaGetSymbolAddress((void**)&eh, g_e_hi);
    cudaGetSymbolAddress((void**)&el, g_e_lo);
    cudaGetSymbolAddress((void**)&xA, g_xA);
    cudaGetSymbolAddress((void**)&xB, g_xB);
    cudaGetSymbolAddress((void**)&pf, g_pf);
    cudaGetSymbolAddress((void**)&pb, g_pb);

    build_kf<<<(int)(((size_t)MI * NI + 255) / 256), 256>>>(A);
    build_kb<<<(int)(((size_t)NI * MI + 255) / 256), 256>>>(A);
    init_x<<<(BDIM * NI + 255) / 256, 256>>>();

    GemmArgs gf;
    gf.Ahi = kfh; gf.Alo = kfl; gf.Bhi = xh; gf.Blo = xl;
    gf.part = pf; gf.Kdim = NI; gf.Ctot = MI; gf.kchunk = NI / FWD_SPLIT;   // 512
    GemmArgs gb;
    gb.Ahi = kbh; gb.Alo = kbl; gb.Bhi = eh; gb.Blo = el;
    gb.part = pb; gb.Kdim = MI; gb.Ctot = NI; gb.kchunk = MI / BWD_SPLIT;   // 512

    float* xcur = xA;
    float* xnxt = xB;
    for (int it = 0; it < NITER; it++) {
        gemm_mma<<<dim3(MI / MT, FWD_SPLIT), 256, SMEM_TOTAL>>>(gf);
        err_conv<<<(BDIM * MI + 255) / 256, 256>>>(y);
        gemm_mma<<<dim3(NI / MT, BWD_SPLIT), 256, SMEM_TOTAL>>>(gb);
        upd_x<<<(BDIM * NI + 255) / 256, 256>>>(xcur, xnxt);
        float* t = xcur; xcur = xnxt; xnxt = t;
    }
    cudaMemcpyAsync(d_out, xcur, (size_t)BDIM * NI * sizeof(float),
                    cudaMemcpyDeviceToDevice);
}